// round 5
// baseline (speedup 1.0000x reference)
#include <cuda_runtime.h>
#include <cstdint>

#define Bn 16
#define Dn 1024
#define Qn 128
#define Hn 1024
#define NEGINF (-1e30f)

// ---------------- scratch (device globals; no allocations) ----------------
__device__ float g_S [Bn*Dn*Qn];   // raw scores
__device__ float g_P [Bn*Dn*Qn];   // S_d2q
__device__ float g_P2[Bn*Dn*Qn];   // S_q2d
__device__ float g_T [Bn*Qn*Hn];   // T[q,h] = sum_d S_q2d[d,q] * U_d[d,h]
__device__ float g_sd[Bn*Dn];
__device__ float g_sq[Bn*Qn];

typedef unsigned long long u64;

__device__ __forceinline__ u64 pk2(float lo, float hi) {
    u64 r; asm("mov.b64 %0,{%1,%2};" : "=l"(r) : "f"(lo), "f"(hi)); return r;
}
__device__ __forceinline__ void upk2(u64 v, float& lo, float& hi) {
    asm("mov.b64 {%0,%1},%2;" : "=f"(lo), "=f"(hi) : "l"(v));
}
__device__ __forceinline__ void fma2(u64& d, u64 a, u64 b) {
    asm("fma.rn.f32x2 %0,%1,%2,%0;" : "+l"(d) : "l"(a), "l"(b));
}

// ---------------- K0: s_d and s_q row dots ----------------
__global__ void k0_rowdots(const float* __restrict__ Ud, const float* __restrict__ Uq,
                           const float* __restrict__ wc)
{
    const int warp = (blockIdx.x * blockDim.x + threadIdx.x) >> 5;
    const int lane = threadIdx.x & 31;
    const int nrows = Bn*Dn + Bn*Qn;
    if (warp >= nrows) return;
    const float* row; const float* w; float* outp;
    if (warp < Bn*Dn) { row = Ud + (size_t)warp * Hn; w = wc;      outp = &g_sd[warp]; }
    else { int r = warp - Bn*Dn; row = Uq + (size_t)r * Hn; w = wc + Hn; outp = &g_sq[r]; }
    float s = 0.f;
#pragma unroll
    for (int j = 0; j < Hn/128; ++j) {
        float4 a  = *(const float4*)(row + (j*32 + lane)*4);
        float4 ww = *(const float4*)(w   + (j*32 + lane)*4);
        s += a.x*ww.x + a.y*ww.y + a.z*ww.z + a.w*ww.w;
    }
#pragma unroll
    for (int o = 16; o; o >>= 1) s += __shfl_xor_sync(0xffffffffu, s, o);
    if (lane == 0) *outp = s;
}

// ---------------- K1: S = (U_d*w_dot) @ U_q^T + s_d + s_q + bias ----------------
// NT GEMM per batch: M=D=1024, N=Q=128, K=H=1024.  Tile 128x128x16.
__global__ void k1_score(const float* __restrict__ Ud, const float* __restrict__ Uq,
                         const float* __restrict__ wc, const float* __restrict__ wcb)
{
    const int b  = blockIdx.y;
    const int m0 = blockIdx.x * 128;
    const float* A  = Ud + ((size_t)b*Dn + m0) * Hn;   // A[m][k]
    const float* Bg = Uq + (size_t)b*Qn*Hn;            // B[n][k]
    const float* wd = wc + 2*Hn;

    __shared__ float As[16][132];
    __shared__ float Bs[16][132];

    const int tid = threadIdx.x;
    const int lm = tid >> 2;
    const int lk = (tid & 3) << 2;
    const int tx = tid & 15, ty = tid >> 4;
    const int n0 = tx*8, mo = ty*8;

    u64 acc[8][4];
#pragma unroll
    for (int i = 0; i < 8; ++i)
#pragma unroll
        for (int j = 0; j < 4; ++j) acc[i][j] = 0ull;

    float4 a0, a1, b0, b1, w4;
    w4 = *(const float4*)(wd + lk);
    a0 = *(const float4*)(A  + (size_t)lm*Hn      + lk);
    a1 = *(const float4*)(A  + (size_t)(lm+64)*Hn + lk);
    b0 = *(const float4*)(Bg + (size_t)lm*Hn      + lk);
    b1 = *(const float4*)(Bg + (size_t)(lm+64)*Hn + lk);
    As[lk+0][lm]    = a0.x*w4.x; As[lk+1][lm]    = a0.y*w4.y; As[lk+2][lm]    = a0.z*w4.z; As[lk+3][lm]    = a0.w*w4.w;
    As[lk+0][lm+64] = a1.x*w4.x; As[lk+1][lm+64] = a1.y*w4.y; As[lk+2][lm+64] = a1.z*w4.z; As[lk+3][lm+64] = a1.w*w4.w;
    Bs[lk+0][lm]    = b0.x;      Bs[lk+1][lm]    = b0.y;      Bs[lk+2][lm]    = b0.z;      Bs[lk+3][lm]    = b0.w;
    Bs[lk+0][lm+64] = b1.x;      Bs[lk+1][lm+64] = b1.y;      Bs[lk+2][lm+64] = b1.z;      Bs[lk+3][lm+64] = b1.w;
    __syncthreads();

    const int NK = Hn/16;
    for (int kt = 1; kt <= NK; ++kt) {
        if (kt < NK) {
            const int k0 = kt*16;
            w4 = *(const float4*)(wd + k0 + lk);
            a0 = *(const float4*)(A  + (size_t)lm*Hn      + k0 + lk);
            a1 = *(const float4*)(A  + (size_t)(lm+64)*Hn + k0 + lk);
            b0 = *(const float4*)(Bg + (size_t)lm*Hn      + k0 + lk);
            b1 = *(const float4*)(Bg + (size_t)(lm+64)*Hn + k0 + lk);
        }
#pragma unroll
        for (int k = 0; k < 16; ++k) {
            const float4 fa0 = *(const float4*)&As[k][mo];
            const float4 fa1 = *(const float4*)&As[k][mo+4];
            const float4 fb0 = *(const float4*)&Bs[k][n0];
            const float4 fb1 = *(const float4*)&Bs[k][n0+4];
            const u64 bb0 = pk2(fb0.x, fb0.y), bb1 = pk2(fb0.z, fb0.w);
            const u64 bb2 = pk2(fb1.x, fb1.y), bb3 = pk2(fb1.z, fb1.w);
            const float av[8] = {fa0.x, fa0.y, fa0.z, fa0.w, fa1.x, fa1.y, fa1.z, fa1.w};
#pragma unroll
            for (int i = 0; i < 8; ++i) {
                const u64 aa = pk2(av[i], av[i]);
                fma2(acc[i][0], aa, bb0); fma2(acc[i][1], aa, bb1);
                fma2(acc[i][2], aa, bb2); fma2(acc[i][3], aa, bb3);
            }
        }
        __syncthreads();
        if (kt < NK) {
            As[lk+0][lm]    = a0.x*w4.x; As[lk+1][lm]    = a0.y*w4.y; As[lk+2][lm]    = a0.z*w4.z; As[lk+3][lm]    = a0.w*w4.w;
            As[lk+0][lm+64] = a1.x*w4.x; As[lk+1][lm+64] = a1.y*w4.y; As[lk+2][lm+64] = a1.z*w4.z; As[lk+3][lm+64] = a1.w*w4.w;
            Bs[lk+0][lm]    = b0.x;      Bs[lk+1][lm]    = b0.y;      Bs[lk+2][lm]    = b0.z;      Bs[lk+3][lm]    = b0.w;
            Bs[lk+0][lm+64] = b1.x;      Bs[lk+1][lm+64] = b1.y;      Bs[lk+2][lm+64] = b1.z;      Bs[lk+3][lm+64] = b1.w;
            __syncthreads();
        }
    }

    const float bias = wcb[0];
    const float4 sq0 = *(const float4*)(g_sq + b*Qn + n0);
    const float4 sq1 = *(const float4*)(g_sq + b*Qn + n0 + 4);
    const float sqv[8] = {sq0.x, sq0.y, sq0.z, sq0.w, sq1.x, sq1.y, sq1.z, sq1.w};
#pragma unroll
    for (int i = 0; i < 8; ++i) {
        const int m = m0 + mo + i;
        const float sdv = g_sd[b*Dn + m] + bias;
        float c[8];
        upk2(acc[i][0], c[0], c[1]); upk2(acc[i][1], c[2], c[3]);
        upk2(acc[i][2], c[4], c[5]); upk2(acc[i][3], c[6], c[7]);
        float* op = g_S + ((size_t)b*Dn + m)*Qn + n0;
        *(float4*)(op)     = make_float4(c[0]+sdv+sqv[0], c[1]+sdv+sqv[1], c[2]+sdv+sqv[2], c[3]+sdv+sqv[3]);
        *(float4*)(op + 4) = make_float4(c[4]+sdv+sqv[4], c[5]+sdv+sqv[5], c[6]+sdv+sqv[6], c[7]+sdv+sqv[7]);
    }
}

// ---------------- K2: row softmax over q (axis -1) -> g_P ----------------
__global__ void k2_rowsoftmax(const int* __restrict__ qmask, const int* __restrict__ dmask)
{
    const int row  = (blockIdx.x * blockDim.x + threadIdx.x) >> 5;
    const int lane = threadIdx.x & 31;
    if (row >= Bn*Dn) return;
    const int b = row >> 10;
    const float4 s = *(const float4*)(g_S + (size_t)row*Qn + lane*4);
    const int dm = dmask[row];
    const int4 qm = *(const int4*)(qmask + b*Qn + lane*4);
    const bool m0v = (dm > 0) && (qm.x > 0);
    const bool m1v = (dm > 0) && (qm.y > 0);
    const bool m2v = (dm > 0) && (qm.z > 0);
    const bool m3v = (dm > 0) && (qm.w > 0);
    const float l0 = m0v ? s.x : NEGINF;
    const float l1 = m1v ? s.y : NEGINF;
    const float l2 = m2v ? s.z : NEGINF;
    const float l3 = m3v ? s.w : NEGINF;
    float mx = fmaxf(fmaxf(l0, l1), fmaxf(l2, l3));
#pragma unroll
    for (int o = 16; o; o >>= 1) mx = fmaxf(mx, __shfl_xor_sync(0xffffffffu, mx, o));
    const float e0 = __expf(l0 - mx), e1 = __expf(l1 - mx);
    const float e2 = __expf(l2 - mx), e3 = __expf(l3 - mx);
    float sm = e0 + e1 + e2 + e3;
#pragma unroll
    for (int o = 16; o; o >>= 1) sm += __shfl_xor_sync(0xffffffffu, sm, o);
    const float inv = 1.f / sm;
    *(float4*)(g_P + (size_t)row*Qn + lane*4) =
        make_float4(m0v ? e0*inv : 0.f, m1v ? e1*inv : 0.f, m2v ? e2*inv : 0.f, m3v ? e3*inv : 0.f);
}

// ---------------- K3: column softmax over d (axis -2) -> g_P2 ----------------
__global__ void __launch_bounds__(1024)
k3_colsoftmax(const int* __restrict__ qmask, const int* __restrict__ dmask)
{
    const int b  = blockIdx.y;
    const int tx = threadIdx.x, ty = threadIdx.y;
    const int q  = blockIdx.x*32 + tx;
    __shared__ float red[32][33];
    const int qm = qmask[b*Qn + q];
    float v[32];
    float mx = -3.0e38f;
#pragma unroll
    for (int j = 0; j < 32; ++j) {
        const int d = ty + j*32;
        const float s = g_S[((size_t)b*Dn + d)*Qn + q];
        const float l = (qm > 0 && dmask[b*Dn + d] > 0) ? s : NEGINF;
        v[j] = l; mx = fmaxf(mx, l);
    }
    red[ty][tx] = mx; __syncthreads();
#pragma unroll
    for (int off = 16; off; off >>= 1) {
        if (ty < off) red[ty][tx] = fmaxf(red[ty][tx], red[ty+off][tx]);
        __syncthreads();
    }
    mx = red[0][tx];
    __syncthreads();
    float se = 0.f;
#pragma unroll
    for (int j = 0; j < 32; ++j) { v[j] = __expf(v[j] - mx); se += v[j]; }
    red[ty][tx] = se; __syncthreads();
#pragma unroll
    for (int off = 16; off; off >>= 1) {
        if (ty < off) red[ty][tx] += red[ty+off][tx];
        __syncthreads();
    }
    const float inv = 1.f / red[0][tx];
#pragma unroll
    for (int j = 0; j < 32; ++j) {
        const int d = ty + j*32;
        const float ind = (qm > 0 && dmask[b*Dn + d] > 0) ? 1.f : 0.f;
        g_P2[((size_t)b*Dn + d)*Qn + q] = v[j]*inv*ind;
    }
}

// ---------------- K4: T[q,h] = sum_d S_q2d[d,q] * U_d[d,h] ----------------
// TN GEMM per batch: M=Q=128, N=H (tiled 128), K=D=1024.
__global__ void k4_T(const float* __restrict__ Ud)
{
    const int b   = blockIdx.y;
    const int n0b = blockIdx.x * 128;
    const float* A  = g_P2 + (size_t)b*Dn*Qn;          // A[k][m], m contiguous
    const float* Bg = Ud   + (size_t)b*Dn*Hn + n0b;    // B[k][n], n contiguous

    __shared__ float As[16][128];
    __shared__ float Bs[16][128];

    const int tid = threadIdx.x;
    const int lk0 = tid >> 5;            // 0..7
    const int lc  = (tid & 31) << 2;     // 0..124
    const int tx = tid & 15, ty = tid >> 4;
    const int n0 = tx*8, mo = ty*8;

    u64 acc[8][4];
#pragma unroll
    for (int i = 0; i < 8; ++i)
#pragma unroll
        for (int j = 0; j < 4; ++j) acc[i][j] = 0ull;

    float4 a0, a1, b0, b1;
    a0 = *(const float4*)(A  + (size_t)(lk0)*Qn   + lc);
    a1 = *(const float4*)(A  + (size_t)(lk0+8)*Qn + lc);
    b0 = *(const float4*)(Bg + (size_t)(lk0)*Hn   + lc);
    b1 = *(const float4*)(Bg + (size_t)(lk0+8)*Hn + lc);
    *(float4*)&As[lk0][lc] = a0; *(float4*)&As[lk0+8][lc] = a1;
    *(float4*)&Bs[lk0][lc] = b0; *(float4*)&Bs[lk0+8][lc] = b1;
    __syncthreads();

    const int NK = Dn/16;
    for (int kt = 1; kt <= NK; ++kt) {
        if (kt < NK) {
            const int k0 = kt*16;
            a0 = *(const float4*)(A  + (size_t)(k0+lk0)*Qn   + lc);
            a1 = *(const float4*)(A  + (size_t)(k0+lk0+8)*Qn + lc);
            b0 = *(const float4*)(Bg + (size_t)(k0+lk0)*Hn   + lc);
            b1 = *(const float4*)(Bg + (size_t)(k0+lk0+8)*Hn + lc);
        }
#pragma unroll
        for (int k = 0; k < 16; ++k) {
            const float4 fa0 = *(const float4*)&As[k][mo];
            const float4 fa1 = *(const float4*)&As[k][mo+4];
            const float4 fb0 = *(const float4*)&Bs[k][n0];
            const float4 fb1 = *(const float4*)&Bs[k][n0+4];
            const u64 bb0 = pk2(fb0.x, fb0.y), bb1 = pk2(fb0.z, fb0.w);
            const u64 bb2 = pk2(fb1.x, fb1.y), bb3 = pk2(fb1.z, fb1.w);
            const float av[8] = {fa0.x, fa0.y, fa0.z, fa0.w, fa1.x, fa1.y, fa1.z, fa1.w};
#pragma unroll
            for (int i = 0; i < 8; ++i) {
                const u64 aa = pk2(av[i], av[i]);
                fma2(acc[i][0], aa, bb0); fma2(acc[i][1], aa, bb1);
                fma2(acc[i][2], aa, bb2); fma2(acc[i][3], aa, bb3);
            }
        }
        __syncthreads();
        if (kt < NK) {
            *(float4*)&As[lk0][lc] = a0; *(float4*)&As[lk0+8][lc] = a1;
            *(float4*)&Bs[lk0][lc] = b0; *(float4*)&Bs[lk0+8][lc] = b1;
            __syncthreads();
        }
    }

#pragma unroll
    for (int i = 0; i < 8; ++i) {
        const int m = mo + i;   // q index (M == 128 exactly)
        float c[8];
        upk2(acc[i][0], c[0], c[1]); upk2(acc[i][1], c[2], c[3]);
        upk2(acc[i][2], c[4], c[5]); upk2(acc[i][3], c[6], c[7]);
        float* op = g_T + ((size_t)b*Qn + m)*Hn + n0b + n0;
        *(float4*)(op)     = make_float4(c[0], c[1], c[2], c[3]);
        *(float4*)(op + 4) = make_float4(c[4], c[5], c[6], c[7]);
    }
}

// ---------------- K5: A_d2q = S_d2q @ U_q ; A_q2d = S_d2q @ T ; write V_d ----
// NN GEMMs per batch sharing A: M=D (tile 128), N=H (tile 64), K=Q=128.
__global__ void k5_out(const float* __restrict__ Ud, const float* __restrict__ Uq,
                       float* __restrict__ out)
{
    const int b   = blockIdx.z;
    const int m0  = blockIdx.y * 128;
    const int n0b = blockIdx.x * 64;
    const float* A  = g_P + ((size_t)b*Dn + m0)*Qn;   // A[m][k]
    const float* B1 = Uq  + (size_t)b*Qn*Hn + n0b;    // [k][n]
    const float* B2 = g_T + (size_t)b*Qn*Hn + n0b;    // [k][n]

    __shared__ float As[16][132];
    __shared__ float Bs1[16][64];
    __shared__ float Bs2[16][64];

    const int tid = threadIdx.x;
    const int lm = tid >> 2, lk = (tid & 3) << 2;     // A loader (transposed)
    const int bk = tid >> 4, bn = (tid & 15) << 2;    // B loader (direct)
    const int tx = tid & 15, ty = tid >> 4;
    const int n0 = tx*4, mo = ty*8;

    u64 ac1[8][2], ac2[8][2];
#pragma unroll
    for (int i = 0; i < 8; ++i) {
        ac1[i][0] = 0ull; ac1[i][1] = 0ull;
        ac2[i][0] = 0ull; ac2[i][1] = 0ull;
    }

    float4 a0, a1, v1, v2;
    a0 = *(const float4*)(A  + (size_t)lm*Qn      + lk);
    a1 = *(const float4*)(A  + (size_t)(lm+64)*Qn + lk);
    v1 = *(const float4*)(B1 + (size_t)bk*Hn + bn);
    v2 = *(const float4*)(B2 + (size_t)bk*Hn + bn);
    As[lk+0][lm]    = a0.x; As[lk+1][lm]    = a0.y; As[lk+2][lm]    = a0.z; As[lk+3][lm]    = a0.w;
    As[lk+0][lm+64] = a1.x; As[lk+1][lm+64] = a1.y; As[lk+2][lm+64] = a1.z; As[lk+3][lm+64] = a1.w;
    *(float4*)&Bs1[bk][bn] = v1;
    *(float4*)&Bs2[bk][bn] = v2;
    __syncthreads();

    const int NK = Qn/16;   // 8
    for (int kt = 1; kt <= NK; ++kt) {
        if (kt < NK) {
            const int k0 = kt*16;
            a0 = *(const float4*)(A  + (size_t)lm*Qn      + k0 + lk);
            a1 = *(const float4*)(A  + (size_t)(lm+64)*Qn + k0 + lk);
            v1 = *(const float4*)(B1 + (size_t)(k0+bk)*Hn + bn);
            v2 = *(const float4*)(B2 + (size_t)(k0+bk)*Hn + bn);
        }
#pragma unroll
        for (int k = 0; k < 16; ++k) {
            const float4 fa0 = *(const float4*)&As[k][mo];
            const float4 fa1 = *(const float4*)&As[k][mo+4];
            const float4 f1  = *(const float4*)&Bs1[k][n0];
            const float4 f2  = *(const float4*)&Bs2[k][n0];
            const u64 p10 = pk2(f1.x, f1.y), p11 = pk2(f1.z, f1.w);
            const u64 p20 = pk2(f2.x, f2.y), p21 = pk2(f2.z, f2.w);
            const float av[8] = {fa0.x, fa0.y, fa0.z, fa0.w, fa1.x, fa1.y, fa1.z, fa1.w};
#pragma unroll
            for (int i = 0; i < 8; ++i) {
                const u64 aa = pk2(av[i], av[i]);
                fma2(ac1[i][0], aa, p10); fma2(ac1[i][1], aa, p11);
                fma2(ac2[i][0], aa, p20); fma2(ac2[i][1], aa, p21);
            }
        }
        __syncthreads();
        if (kt < NK) {
            As[lk+0][lm]    = a0.x; As[lk+1][lm]    = a0.y; As[lk+2][lm]    = a0.z; As[lk+3][lm]    = a0.w;
            As[lk+0][lm+64] = a1.x; As[lk+1][lm+64] = a1.y; As[lk+2][lm+64] = a1.z; As[lk+3][lm+64] = a1.w;
            *(float4*)&Bs1[bk][bn] = v1;
            *(float4*)&Bs2[bk][bn] = v2;
            __syncthreads();
        }
    }

#pragma unroll
    for (int i = 0; i < 8; ++i) {
        const int m = m0 + mo + i;
        const float4 u = *(const float4*)(Ud + ((size_t)b*Dn + m)*Hn + n0b + n0);
        float c1[4], c2[4];
        upk2(ac1[i][0], c1[0], c1[1]); upk2(ac1[i][1], c1[2], c1[3]);
        upk2(ac2[i][0], c2[0], c2[1]); upk2(ac2[i][1], c2[2], c2[3]);
        float* op = out + ((size_t)b*Dn + m)*(4*Hn) + n0b + n0;
        *(float4*)(op)        = u;
        *(float4*)(op +   Hn) = make_float4(c1[0], c1[1], c1[2], c1[3]);
        *(float4*)(op + 2*Hn) = make_float4(u.x*c1[0], u.y*c1[1], u.z*c1[2], u.w*c1[3]);
        *(float4*)(op + 3*Hn) = make_float4(u.x*c2[0], u.y*c2[1], u.z*c2[2], u.w*c2[3]);
    }
}

// ---------------- launch ----------------
extern "C" void kernel_launch(void* const* d_in, const int* in_sizes, int n_in,
                              void* d_out, int out_size)
{
    const float* Ud    = (const float*)d_in[0];
    const float* Uq    = (const float*)d_in[1];
    const float* wc    = (const float*)d_in[2];
    const float* wcb   = (const float*)d_in[3];
    const int*   qmask = (const int*)d_in[4];
    const int*   dmask = (const int*)d_in[5];
    float* out = (float*)d_out;

    (void)in_sizes; (void)n_in; (void)out_size;

    const int nrows = Bn*Dn + Bn*Qn;
    k0_rowdots  <<<(nrows + 7)/8, 256>>>(Ud, Uq, wc);
    k1_score    <<<dim3(Dn/128, Bn), 256>>>(Ud, Uq, wc, wcb);
    k2_rowsoftmax<<<(Bn*Dn)/8, 256>>>(qmask, dmask);
    k3_colsoftmax<<<dim3(Qn/32, Bn), dim3(32, 32)>>>(qmask, dmask);
    k4_T        <<<dim3(Hn/128, Bn), 256>>>(Ud);
    k5_out      <<<dim3(Hn/64, Dn/128, Bn), 256>>>(Ud, Uq, out);
}

// round 7
// speedup vs baseline: 1.0045x; 1.0045x over previous
#include <cuda_runtime.h>
#include <cstdint>

#define Bn 16
#define Dn 1024
#define Qn 128
#define Hn 1024
#define NEGINF (-1e30f)

// ---------------- scratch (device globals; no allocations) ----------------
__device__ float g_S [Bn*Dn*Qn];   // raw scores
__device__ float g_P [Bn*Dn*Qn];   // S_d2q
__device__ float g_P2[Bn*Dn*Qn];   // S_q2d
__device__ float g_T [Bn*Qn*Hn];   // T[q,h] = sum_d S_q2d[d,q] * U_d[d,h]
__device__ float g_sd[Bn*Dn];
__device__ float g_sq[Bn*Qn];

typedef unsigned long long u64;

__device__ __forceinline__ u64 pk2(float lo, float hi) {
    u64 r; asm("mov.b64 %0,{%1,%2};" : "=l"(r) : "f"(lo), "f"(hi)); return r;
}
__device__ __forceinline__ void upk2(u64 v, float& lo, float& hi) {
    asm("mov.b64 {%0,%1},%2;" : "=f"(lo), "=f"(hi) : "l"(v));
}
__device__ __forceinline__ void fma2(u64& d, u64 a, u64 b) {
    asm("fma.rn.f32x2 %0,%1,%2,%0;" : "+l"(d) : "l"(a), "l"(b));
}

// ---------------- K0: s_d and s_q row dots ----------------
__global__ void k0_rowdots(const float* __restrict__ Ud, const float* __restrict__ Uq,
                           const float* __restrict__ wc)
{
    const int warp = (blockIdx.x * blockDim.x + threadIdx.x) >> 5;
    const int lane = threadIdx.x & 31;
    const int nrows = Bn*Dn + Bn*Qn;
    if (warp >= nrows) return;
    const float* row; const float* w; float* outp;
    if (warp < Bn*Dn) { row = Ud + (size_t)warp * Hn; w = wc;      outp = &g_sd[warp]; }
    else { int r = warp - Bn*Dn; row = Uq + (size_t)r * Hn; w = wc + Hn; outp = &g_sq[r]; }
    float s = 0.f;
#pragma unroll
    for (int j = 0; j < Hn/128; ++j) {
        float4 a  = *(const float4*)(row + (j*32 + lane)*4);
        float4 ww = *(const float4*)(w   + (j*32 + lane)*4);
        s += a.x*ww.x + a.y*ww.y + a.z*ww.z + a.w*ww.w;
    }
#pragma unroll
    for (int o = 16; o; o >>= 1) s += __shfl_xor_sync(0xffffffffu, s, o);
    if (lane == 0) *outp = s;
}

// ---------------- K1: S = (U_d*w_dot) @ U_q^T + s_d + s_q + bias ----------------
// NT GEMM per batch: M=D=1024, N=Q=128, K=H=1024.  Tile 128x128x16.
__global__ void k1_score(const float* __restrict__ Ud, const float* __restrict__ Uq,
                         const float* __restrict__ wc, const float* __restrict__ wcb)
{
    const int b  = blockIdx.y;
    const int m0 = blockIdx.x * 128;
    const float* A  = Ud + ((size_t)b*Dn + m0) * Hn;   // A[m][k]
    const float* Bg = Uq + (size_t)b*Qn*Hn;            // B[n][k]
    const float* wd = wc + 2*Hn;

    __shared__ float As[16][132];
    __shared__ float Bs[16][132];

    const int tid = threadIdx.x;
    const int lm = tid >> 2;
    const int lk = (tid & 3) << 2;
    const int tx = tid & 15, ty = tid >> 4;
    const int n0 = tx*8, mo = ty*8;

    u64 acc[8][4];
#pragma unroll
    for (int i = 0; i < 8; ++i)
#pragma unroll
        for (int j = 0; j < 4; ++j) acc[i][j] = 0ull;

    float4 a0, a1, b0, b1, w4;
    w4 = *(const float4*)(wd + lk);
    a0 = *(const float4*)(A  + (size_t)lm*Hn      + lk);
    a1 = *(const float4*)(A  + (size_t)(lm+64)*Hn + lk);
    b0 = *(const float4*)(Bg + (size_t)lm*Hn      + lk);
    b1 = *(const float4*)(Bg + (size_t)(lm+64)*Hn + lk);
    As[lk+0][lm]    = a0.x*w4.x; As[lk+1][lm]    = a0.y*w4.y; As[lk+2][lm]    = a0.z*w4.z; As[lk+3][lm]    = a0.w*w4.w;
    As[lk+0][lm+64] = a1.x*w4.x; As[lk+1][lm+64] = a1.y*w4.y; As[lk+2][lm+64] = a1.z*w4.z; As[lk+3][lm+64] = a1.w*w4.w;
    Bs[lk+0][lm]    = b0.x;      Bs[lk+1][lm]    = b0.y;      Bs[lk+2][lm]    = b0.z;      Bs[lk+3][lm]    = b0.w;
    Bs[lk+0][lm+64] = b1.x;      Bs[lk+1][lm+64] = b1.y;      Bs[lk+2][lm+64] = b1.z;      Bs[lk+3][lm+64] = b1.w;
    __syncthreads();

    const int NK = Hn/16;
    for (int kt = 1; kt <= NK; ++kt) {
        if (kt < NK) {
            const int k0 = kt*16;
            w4 = *(const float4*)(wd + k0 + lk);
            a0 = *(const float4*)(A  + (size_t)lm*Hn      + k0 + lk);
            a1 = *(const float4*)(A  + (size_t)(lm+64)*Hn + k0 + lk);
            b0 = *(const float4*)(Bg + (size_t)lm*Hn      + k0 + lk);
            b1 = *(const float4*)(Bg + (size_t)(lm+64)*Hn + k0 + lk);
        }
#pragma unroll
        for (int k = 0; k < 16; ++k) {
            const float4 fa0 = *(const float4*)&As[k][mo];
            const float4 fa1 = *(const float4*)&As[k][mo+4];
            const float4 fb0 = *(const float4*)&Bs[k][n0];
            const float4 fb1 = *(const float4*)&Bs[k][n0+4];
            const u64 bb0 = pk2(fb0.x, fb0.y), bb1 = pk2(fb0.z, fb0.w);
            const u64 bb2 = pk2(fb1.x, fb1.y), bb3 = pk2(fb1.z, fb1.w);
            const float av[8] = {fa0.x, fa0.y, fa0.z, fa0.w, fa1.x, fa1.y, fa1.z, fa1.w};
#pragma unroll
            for (int i = 0; i < 8; ++i) {
                const u64 aa = pk2(av[i], av[i]);
                fma2(acc[i][0], aa, bb0); fma2(acc[i][1], aa, bb1);
                fma2(acc[i][2], aa, bb2); fma2(acc[i][3], aa, bb3);
            }
        }
        __syncthreads();
        if (kt < NK) {
            As[lk+0][lm]    = a0.x*w4.x; As[lk+1][lm]    = a0.y*w4.y; As[lk+2][lm]    = a0.z*w4.z; As[lk+3][lm]    = a0.w*w4.w;
            As[lk+0][lm+64] = a1.x*w4.x; As[lk+1][lm+64] = a1.y*w4.y; As[lk+2][lm+64] = a1.z*w4.z; As[lk+3][lm+64] = a1.w*w4.w;
            Bs[lk+0][lm]    = b0.x;      Bs[lk+1][lm]    = b0.y;      Bs[lk+2][lm]    = b0.z;      Bs[lk+3][lm]    = b0.w;
            Bs[lk+0][lm+64] = b1.x;      Bs[lk+1][lm+64] = b1.y;      Bs[lk+2][lm+64] = b1.z;      Bs[lk+3][lm+64] = b1.w;
            __syncthreads();
        }
    }

    const float bias = wcb[0];
    const float4 sq0 = *(const float4*)(g_sq + b*Qn + n0);
    const float4 sq1 = *(const float4*)(g_sq + b*Qn + n0 + 4);
    const float sqv[8] = {sq0.x, sq0.y, sq0.z, sq0.w, sq1.x, sq1.y, sq1.z, sq1.w};
#pragma unroll
    for (int i = 0; i < 8; ++i) {
        const int m = m0 + mo + i;
        const float sdv = g_sd[b*Dn + m] + bias;
        float c[8];
        upk2(acc[i][0], c[0], c[1]); upk2(acc[i][1], c[2], c[3]);
        upk2(acc[i][2], c[4], c[5]); upk2(acc[i][3], c[6], c[7]);
        float* op = g_S + ((size_t)b*Dn + m)*Qn + n0;
        *(float4*)(op)     = make_float4(c[0]+sdv+sqv[0], c[1]+sdv+sqv[1], c[2]+sdv+sqv[2], c[3]+sdv+sqv[3]);
        *(float4*)(op + 4) = make_float4(c[4]+sdv+sqv[4], c[5]+sdv+sqv[5], c[6]+sdv+sqv[6], c[7]+sdv+sqv[7]);
    }
}

// ---------------- K2: row softmax over q (axis -1) -> g_P ----------------
__global__ void k2_rowsoftmax(const int* __restrict__ qmask, const int* __restrict__ dmask)
{
    const int row  = (blockIdx.x * blockDim.x + threadIdx.x) >> 5;
    const int lane = threadIdx.x & 31;
    if (row >= Bn*Dn) return;
    const int b = row >> 10;
    const float4 s = *(const float4*)(g_S + (size_t)row*Qn + lane*4);
    const int dm = dmask[row];
    const int4 qm = *(const int4*)(qmask + b*Qn + lane*4);
    const bool m0v = (dm > 0) && (qm.x > 0);
    const bool m1v = (dm > 0) && (qm.y > 0);
    const bool m2v = (dm > 0) && (qm.z > 0);
    const bool m3v = (dm > 0) && (qm.w > 0);
    const float l0 = m0v ? s.x : NEGINF;
    const float l1 = m1v ? s.y : NEGINF;
    const float l2 = m2v ? s.z : NEGINF;
    const float l3 = m3v ? s.w : NEGINF;
    float mx = fmaxf(fmaxf(l0, l1), fmaxf(l2, l3));
#pragma unroll
    for (int o = 16; o; o >>= 1) mx = fmaxf(mx, __shfl_xor_sync(0xffffffffu, mx, o));
    const float e0 = __expf(l0 - mx), e1 = __expf(l1 - mx);
    const float e2 = __expf(l2 - mx), e3 = __expf(l3 - mx);
    float sm = e0 + e1 + e2 + e3;
#pragma unroll
    for (int o = 16; o; o >>= 1) sm += __shfl_xor_sync(0xffffffffu, sm, o);
    const float inv = 1.f / sm;
    *(float4*)(g_P + (size_t)row*Qn + lane*4) =
        make_float4(m0v ? e0*inv : 0.f, m1v ? e1*inv : 0.f, m2v ? e2*inv : 0.f, m3v ? e3*inv : 0.f);
}

// ---------------- K3: column softmax over d (axis -2) -> g_P2 ----------------
__global__ void __launch_bounds__(1024)
k3_colsoftmax(const int* __restrict__ qmask, const int* __restrict__ dmask)
{
    const int b  = blockIdx.y;
    const int tx = threadIdx.x, ty = threadIdx.y;
    const int q  = blockIdx.x*32 + tx;
    __shared__ float red[32][33];
    const int qm = qmask[b*Qn + q];
    float v[32];
    float mx = -3.0e38f;
#pragma unroll
    for (int j = 0; j < 32; ++j) {
        const int d = ty + j*32;
        const float s = g_S[((size_t)b*Dn + d)*Qn + q];
        const float l = (qm > 0 && dmask[b*Dn + d] > 0) ? s : NEGINF;
        v[j] = l; mx = fmaxf(mx, l);
    }
    red[ty][tx] = mx; __syncthreads();
#pragma unroll
    for (int off = 16; off; off >>= 1) {
        if (ty < off) red[ty][tx] = fmaxf(red[ty][tx], red[ty+off][tx]);
        __syncthreads();
    }
    mx = red[0][tx];
    __syncthreads();
    float se = 0.f;
#pragma unroll
    for (int j = 0; j < 32; ++j) { v[j] = __expf(v[j] - mx); se += v[j]; }
    red[ty][tx] = se; __syncthreads();
#pragma unroll
    for (int off = 16; off; off >>= 1) {
        if (ty < off) red[ty][tx] += red[ty+off][tx];
        __syncthreads();
    }
    const float inv = 1.f / red[0][tx];
#pragma unroll
    for (int j = 0; j < 32; ++j) {
        const int d = ty + j*32;
        const float ind = (qm > 0 && dmask[b*Dn + d] > 0) ? 1.f : 0.f;
        g_P2[((size_t)b*Dn + d)*Qn + q] = v[j]*inv*ind;
    }
}

// ---------------- K4: T[q,h] = sum_d S_q2d[d,q] * U_d[d,h] ----------------
// TN GEMM per batch: M=Q=128, N=H (tiled 128), K=D=1024.
__global__ void k4_T(const float* __restrict__ Ud)
{
    const int b   = blockIdx.y;
    const int n0b = blockIdx.x * 128;
    const float* A  = g_P2 + (size_t)b*Dn*Qn;          // A[k][m], m contiguous
    const float* Bg = Ud   + (size_t)b*Dn*Hn + n0b;    // B[k][n], n contiguous

    __shared__ float As[16][128];
    __shared__ float Bs[16][128];

    const int tid = threadIdx.x;
    const int lk0 = tid >> 5;            // 0..7
    const int lc  = (tid & 31) << 2;     // 0..124
    const int tx = tid & 15, ty = tid >> 4;
    const int n0 = tx*8, mo = ty*8;

    u64 acc[8][4];
#pragma unroll
    for (int i = 0; i < 8; ++i)
#pragma unroll
        for (int j = 0; j < 4; ++j) acc[i][j] = 0ull;

    float4 a0, a1, b0, b1;
    a0 = *(const float4*)(A  + (size_t)(lk0)*Qn   + lc);
    a1 = *(const float4*)(A  + (size_t)(lk0+8)*Qn + lc);
    b0 = *(const float4*)(Bg + (size_t)(lk0)*Hn   + lc);
    b1 = *(const float4*)(Bg + (size_t)(lk0+8)*Hn + lc);
    *(float4*)&As[lk0][lc] = a0; *(float4*)&As[lk0+8][lc] = a1;
    *(float4*)&Bs[lk0][lc] = b0; *(float4*)&Bs[lk0+8][lc] = b1;
    __syncthreads();

    const int NK = Dn/16;
    for (int kt = 1; kt <= NK; ++kt) {
        if (kt < NK) {
            const int k0 = kt*16;
            a0 = *(const float4*)(A  + (size_t)(k0+lk0)*Qn   + lc);
            a1 = *(const float4*)(A  + (size_t)(k0+lk0+8)*Qn + lc);
            b0 = *(const float4*)(Bg + (size_t)(k0+lk0)*Hn   + lc);
            b1 = *(const float4*)(Bg + (size_t)(k0+lk0+8)*Hn + lc);
        }
#pragma unroll
        for (int k = 0; k < 16; ++k) {
            const float4 fa0 = *(const float4*)&As[k][mo];
            const float4 fa1 = *(const float4*)&As[k][mo+4];
            const float4 fb0 = *(const float4*)&Bs[k][n0];
            const float4 fb1 = *(const float4*)&Bs[k][n0+4];
            const u64 bb0 = pk2(fb0.x, fb0.y), bb1 = pk2(fb0.z, fb0.w);
            const u64 bb2 = pk2(fb1.x, fb1.y), bb3 = pk2(fb1.z, fb1.w);
            const float av[8] = {fa0.x, fa0.y, fa0.z, fa0.w, fa1.x, fa1.y, fa1.z, fa1.w};
#pragma unroll
            for (int i = 0; i < 8; ++i) {
                const u64 aa = pk2(av[i], av[i]);
                fma2(acc[i][0], aa, bb0); fma2(acc[i][1], aa, bb1);
                fma2(acc[i][2], aa, bb2); fma2(acc[i][3], aa, bb3);
            }
        }
        __syncthreads();
        if (kt < NK) {
            *(float4*)&As[lk0][lc] = a0; *(float4*)&As[lk0+8][lc] = a1;
            *(float4*)&Bs[lk0][lc] = b0; *(float4*)&Bs[lk0+8][lc] = b1;
            __syncthreads();
        }
    }

#pragma unroll
    for (int i = 0; i < 8; ++i) {
        const int m = mo + i;   // q index (M == 128 exactly)
        float c[8];
        upk2(acc[i][0], c[0], c[1]); upk2(acc[i][1], c[2], c[3]);
        upk2(acc[i][2], c[4], c[5]); upk2(acc[i][3], c[6], c[7]);
        float* op = g_T + ((size_t)b*Qn + m)*Hn + n0b + n0;
        *(float4*)(op)     = make_float4(c[0], c[1], c[2], c[3]);
        *(float4*)(op + 4) = make_float4(c[4], c[5], c[6], c[7]);
    }
}

// ---------------- K5: A_d2q = S_d2q @ U_q ; A_q2d = S_d2q @ T ; write V_d ----
// NN GEMMs per batch sharing A: M=D (tile 128), N=H (tile 64), K=Q=128.
__global__ void k5_out(const float* __restrict__ Ud, const float* __restrict__ Uq,
                       float* __restrict__ out)
{
    const int b   = blockIdx.z;
    const int m0  = blockIdx.y * 128;
    const int n0b = blockIdx.x * 64;
    const float* A  = g_P + ((size_t)b*Dn + m0)*Qn;   // A[m][k]
    const float* B1 = Uq  + (size_t)b*Qn*Hn + n0b;    // [k][n]
    const float* B2 = g_T + (size_t)b*Qn*Hn + n0b;    // [k][n]

    __shared__ float As[16][132];
    __shared__ float Bs1[16][64];
    __shared__ float Bs2[16][64];

    const int tid = threadIdx.x;
    const int lm = tid >> 2, lk = (tid & 3) << 2;     // A loader (transposed)
    const int bk = tid >> 4, bn = (tid & 15) << 2;    // B loader (direct)
    const int tx = tid & 15, ty = tid >> 4;
    const int n0 = tx*4, mo = ty*8;

    u64 ac1[8][2], ac2[8][2];
#pragma unroll
    for (int i = 0; i < 8; ++i) {
        ac1[i][0] = 0ull; ac1[i][1] = 0ull;
        ac2[i][0] = 0ull; ac2[i][1] = 0ull;
    }

    float4 a0, a1, v1, v2;
    a0 = *(const float4*)(A  + (size_t)lm*Qn      + lk);
    a1 = *(const float4*)(A  + (size_t)(lm+64)*Qn + lk);
    v1 = *(const float4*)(B1 + (size_t)bk*Hn + bn);
    v2 = *(const float4*)(B2 + (size_t)bk*Hn + bn);
    As[lk+0][lm]    = a0.x; As[lk+1][lm]    = a0.y; As[lk+2][lm]    = a0.z; As[lk+3][lm]    = a0.w;
    As[lk+0][lm+64] = a1.x; As[lk+1][lm+64] = a1.y; As[lk+2][lm+64] = a1.z; As[lk+3][lm+64] = a1.w;
    *(float4*)&Bs1[bk][bn] = v1;
    *(float4*)&Bs2[bk][bn] = v2;
    __syncthreads();

    const int NK = Qn/16;   // 8
    for (int kt = 1; kt <= NK; ++kt) {
        if (kt < NK) {
            const int k0 = kt*16;
            a0 = *(const float4*)(A  + (size_t)lm*Qn      + k0 + lk);
            a1 = *(const float4*)(A  + (size_t)(lm+64)*Qn + k0 + lk);
            v1 = *(const float4*)(B1 + (size_t)(k0+bk)*Hn + bn);
            v2 = *(const float4*)(B2 + (size_t)(k0+bk)*Hn + bn);
        }
#pragma unroll
        for (int k = 0; k < 16; ++k) {
            const float4 fa0 = *(const float4*)&As[k][mo];
            const float4 fa1 = *(const float4*)&As[k][mo+4];
            const float4 f1  = *(const float4*)&Bs1[k][n0];
            const float4 f2  = *(const float4*)&Bs2[k][n0];
            const u64 p10 = pk2(f1.x, f1.y), p11 = pk2(f1.z, f1.w);
            const u64 p20 = pk2(f2.x, f2.y), p21 = pk2(f2.z, f2.w);
            const float av[8] = {fa0.x, fa0.y, fa0.z, fa0.w, fa1.x, fa1.y, fa1.z, fa1.w};
#pragma unroll
            for (int i = 0; i < 8; ++i) {
                const u64 aa = pk2(av[i], av[i]);
                fma2(ac1[i][0], aa, p10); fma2(ac1[i][1], aa, p11);
                fma2(ac2[i][0], aa, p20); fma2(ac2[i][1], aa, p21);
            }
        }
        __syncthreads();
        if (kt < NK) {
            As[lk+0][lm]    = a0.x; As[lk+1][lm]    = a0.y; As[lk+2][lm]    = a0.z; As[lk+3][lm]    = a0.w;
            As[lk+0][lm+64] = a1.x; As[lk+1][lm+64] = a1.y; As[lk+2][lm+64] = a1.z; As[lk+3][lm+64] = a1.w;
            *(float4*)&Bs1[bk][bn] = v1;
            *(float4*)&Bs2[bk][bn] = v2;
            __syncthreads();
        }
    }

#pragma unroll
    for (int i = 0; i < 8; ++i) {
        const int m = m0 + mo + i;
        const float4 u = *(const float4*)(Ud + ((size_t)b*Dn + m)*Hn + n0b + n0);
        float c1[4], c2[4];
        upk2(ac1[i][0], c1[0], c1[1]); upk2(ac1[i][1], c1[2], c1[3]);
        upk2(ac2[i][0], c2[0], c2[1]); upk2(ac2[i][1], c2[2], c2[3]);
        float* op = out + ((size_t)b*Dn + m)*(4*Hn) + n0b + n0;
        *(float4*)(op)        = u;
        *(float4*)(op +   Hn) = make_float4(c1[0], c1[1], c1[2], c1[3]);
        *(float4*)(op + 2*Hn) = make_float4(u.x*c1[0], u.y*c1[1], u.z*c1[2], u.w*c1[3]);
        *(float4*)(op + 3*Hn) = make_float4(u.x*c2[0], u.y*c2[1], u.z*c2[2], u.w*c2[3]);
    }
}

// ---------------- launch ----------------
extern "C" void kernel_launch(void* const* d_in, const int* in_sizes, int n_in,
                              void* d_out, int out_size)
{
    const float* Ud    = (const float*)d_in[0];
    const float* Uq    = (const float*)d_in[1];
    const float* wc    = (const float*)d_in[2];
    const float* wcb   = (const float*)d_in[3];
    const int*   qmask = (const int*)d_in[4];
    const int*   dmask = (const int*)d_in[5];
    float* out = (float*)d_out;

    (void)in_sizes; (void)n_in; (void)out_size;

    const int nrows = Bn*Dn + Bn*Qn;
    k0_rowdots  <<<(nrows + 7)/8, 256>>>(Ud, Uq, wc);
    k1_score    <<<dim3(Dn/128, Bn), 256>>>(Ud, Uq, wc, wcb);
    k2_rowsoftmax<<<(Bn*Dn)/8, 256>>>(qmask, dmask);
    k3_colsoftmax<<<dim3(Qn/32, Bn), dim3(32, 32)>>>(qmask, dmask);
    k4_T        <<<dim3(Hn/128, Bn), 256>>>(Ud);
    k5_out      <<<dim3(Hn/64, Dn/128, Bn), 256>>>(Ud, Uq, out);
}

// round 11
// speedup vs baseline: 1.1044x; 1.0995x over previous
#include <cuda_runtime.h>
#include <cuda_bf16.h>
#include <cstdint>

#define Bn 16
#define Dn 1024
#define Qn 128
#define Hn 1024
#define NEGINF (-1e30f)

// ---------------- scratch (device globals; no allocations) ----------------
__device__ float g_S  [Bn*Dn*Qn];   // raw scores [b][d][q]
__device__ float g_P  [Bn*Dn*Qn];   // S_d2q      [b][d][q]
__device__ float g_P2t[Bn*Qn*Dn];   // S_q2d^T    [b][q][d]
__device__ float g_Tt [Bn*Hn*Qn];   // T^T        [b][h][q]
__device__ float g_sd [Bn*Dn];
__device__ float g_sq [Bn*Qn];

// ---------------- helpers ----------------
__device__ __forceinline__ uint32_t smem_u32(const void* p){
    uint32_t a;
    asm("{ .reg .u64 t; cvta.to.shared.u64 t, %1; cvt.u32.u64 %0, t; }" : "=r"(a) : "l"(p));
    return a;
}
__device__ __forceinline__ void ldm4(uint32_t r[4], uint32_t addr){
    asm volatile("ldmatrix.sync.aligned.m8n8.x4.shared.b16 {%0,%1,%2,%3},[%4];"
        : "=r"(r[0]),"=r"(r[1]),"=r"(r[2]),"=r"(r[3]) : "r"(addr));
}
__device__ __forceinline__ void mma16816(float c[4], const uint32_t a[4], uint32_t b0, uint32_t b1){
    asm volatile("mma.sync.aligned.m16n8k16.row.col.f32.bf16.bf16.f32 "
        "{%0,%1,%2,%3},{%4,%5,%6,%7},{%8,%9},{%0,%1,%2,%3};"
        : "+f"(c[0]),"+f"(c[1]),"+f"(c[2]),"+f"(c[3])
        : "r"(a[0]),"r"(a[1]),"r"(a[2]),"r"(a[3]),"r"(b0),"r"(b1));
}
__device__ __forceinline__ void split2(float x0, float x1, uint32_t& hi, uint32_t& lo){
    __nv_bfloat16 h0 = __float2bfloat16(x0), h1 = __float2bfloat16(x1);
    float r0 = x0 - __bfloat162float(h0), r1 = x1 - __bfloat162float(h1);
    __nv_bfloat16 l0 = __float2bfloat16(r0), l1 = __float2bfloat16(r1);
    hi = (uint32_t)__bfloat16_as_ushort(h0) | ((uint32_t)__bfloat16_as_ushort(h1)<<16);
    lo = (uint32_t)__bfloat16_as_ushort(l0) | ((uint32_t)__bfloat16_as_ushort(l1)<<16);
}

// smem tiles: bf16 [128 rows][32 k] with row stride 40 bf16 (80 B). 4 tiles:
#define TAH 0
#define TAL 10240
#define TBH 20480
#define TBL 30720
#define TILES_BYTES 40960
#define STG_OFF 40960          // fp32 staging [32][132] = 16896 B (k4/k5a only)

// load 128x32 fp32 K-major tile into regs (4 float4/thread, 256 threads)
__device__ __forceinline__ void load4(const float* src, size_t ld, int tid, float4 v[4]){
    const float* p = src + (size_t)(tid>>1)*ld + (tid&1)*16;
#pragma unroll
    for (int j=0;j<4;j++) v[j] = *(const float4*)(p + j*4);
}
// split regs -> hi/lo bf16 tiles
__device__ __forceinline__ void store_split(const float4 v[4], char* sm, int hiOff, int loOff, int tid){
    uint32_t h[8], l[8];
#pragma unroll
    for (int j=0;j<4;j++){
        split2(v[j].x,v[j].y,h[2*j],l[2*j]);
        split2(v[j].z,v[j].w,h[2*j+1],l[2*j+1]);
    }
    const int off = (tid>>1)*80 + (tid&1)*32;
    *(uint4*)(sm + hiOff + off)      = make_uint4(h[0],h[1],h[2],h[3]);
    *(uint4*)(sm + hiOff + off + 16) = make_uint4(h[4],h[5],h[6],h[7]);
    *(uint4*)(sm + loOff + off)      = make_uint4(l[0],l[1],l[2],l[3]);
    *(uint4*)(sm + loOff + off + 16) = make_uint4(l[4],l[5],l[6],l[7]);
}
// staged transpose path: gmem [32 k-rows][128 cols] -> regs -> stg -> tiles[col][k]
__device__ __forceinline__ void load_stage(const float* src, size_t ld, int tid, float4 v[4]){
#pragma unroll
    for (int p=0;p<4;p++){
        const int idx = p*256 + tid;
        v[p] = *(const float4*)(src + (size_t)(idx>>5)*ld + (idx&31)*4);
    }
}
__device__ __forceinline__ void store_stage(const float4 v[4], float* stg, int tid){
#pragma unroll
    for (int p=0;p<4;p++){
        const int idx = p*256 + tid;
        *(float4*)(stg + (idx>>5)*132 + (idx&31)*4) = v[p];
    }
}
__device__ __forceinline__ void trans_convert(const float* stg, char* sm, int hiOff, int loOff, int tid){
    const int h = tid>>1, kb = (tid&1)*16;
#pragma unroll
    for (int j=0;j<8;j++){
        const int k = kb + 2*j;
        uint32_t hh, ll;
        split2(stg[k*132 + h], stg[(k+1)*132 + h], hh, ll);
        *(uint32_t*)(sm + hiOff + h*80 + k*2) = hh;
        *(uint32_t*)(sm + loOff + h*80 + k*2) = ll;
    }
}

// one 32-k chunk of 128x128 MMA, 3-pass bf16 split. 8 warps, warp tile 32x64.
__device__ __forceinline__ void mma_chunk(uint32_t AH, uint32_t AL, uint32_t BH, uint32_t BL,
                                          float acc[16][4], int lane, int wm, int wn)
{
    const int r16 = lane & 15;
    const int c8  = (lane >> 4) * 8;
#pragma unroll
    for (int kk = 0; kk < 32; kk += 16){
        uint32_t Ah[2][4], Al[2][4];
#pragma unroll
        for (int mi = 0; mi < 2; ++mi){
            const uint32_t off = (uint32_t)((wm + mi*16 + r16)*80 + (kk + c8)*2);
            ldm4(Ah[mi], AH + off);
            ldm4(Al[mi], AL + off);
        }
#pragma unroll
        for (int g = 0; g < 4; ++g){
            const uint32_t off = (uint32_t)((wn + g*16 + r16)*80 + (kk + c8)*2);
            uint32_t bh[4], bl[4];
            ldm4(bh, BH + off);
            ldm4(bl, BL + off);
#pragma unroll
            for (int mi = 0; mi < 2; ++mi){
                mma16816(acc[mi*8+2*g],   Ah[mi], bh[0], bh[2]);
                mma16816(acc[mi*8+2*g+1], Ah[mi], bh[1], bh[3]);
                mma16816(acc[mi*8+2*g],   Ah[mi], bl[0], bl[2]);
                mma16816(acc[mi*8+2*g+1], Ah[mi], bl[1], bl[3]);
                mma16816(acc[mi*8+2*g],   Al[mi], bh[0], bh[2]);
                mma16816(acc[mi*8+2*g+1], Al[mi], bh[1], bh[3]);
            }
        }
    }
}

// ---------------- K0: s_d and s_q row dots ----------------
__global__ void k0_rowdots(const float* __restrict__ Ud, const float* __restrict__ Uq,
                           const float* __restrict__ wc)
{
    const int warp = (blockIdx.x * blockDim.x + threadIdx.x) >> 5;
    const int lane = threadIdx.x & 31;
    const int nrows = Bn*Dn + Bn*Qn;
    if (warp >= nrows) return;
    const float* row; const float* w; float* outp;
    if (warp < Bn*Dn) { row = Ud + (size_t)warp * Hn; w = wc;      outp = &g_sd[warp]; }
    else { int r = warp - Bn*Dn; row = Uq + (size_t)r * Hn; w = wc + Hn; outp = &g_sq[r]; }
    float s = 0.f;
#pragma unroll
    for (int j = 0; j < Hn/128; ++j) {
        float4 a  = *(const float4*)(row + (j*32 + lane)*4);
        float4 ww = *(const float4*)(w   + (j*32 + lane)*4);
        s += a.x*ww.x + a.y*ww.y + a.z*ww.z + a.w*ww.w;
    }
#pragma unroll
    for (int o = 16; o; o >>= 1) s += __shfl_xor_sync(0xffffffffu, s, o);
    if (lane == 0) *outp = s;
}

// ---------------- K1: S = (Ud*w)@Uq^T + s_d + s_q + b  (bf16 split MMA) ----------------
// grid (8, 16), 256 thr, dsmem 40960. NT, both operands K-major direct.
__global__ void __launch_bounds__(256)
k1_score(const float* __restrict__ Ud, const float* __restrict__ Uq,
         const float* __restrict__ wc, const float* __restrict__ wcb)
{
    extern __shared__ __align__(16) char sm[];
    const int tid = threadIdx.x, lane = tid&31, wid = tid>>5;
    const int b = blockIdx.y, m0 = blockIdx.x*128;
    const int wm = (wid&3)*32, wn = (wid>>2)*64;
    const uint32_t sb = smem_u32(sm);

    const float* Asrc = Ud + ((size_t)b*Dn + m0)*Hn;
    const float* Bsrc = Uq + (size_t)b*Qn*Hn;
    const float* wd = wc + 2*Hn;

    float acc[16][4];
#pragma unroll
    for (int i=0;i<16;i++){acc[i][0]=acc[i][1]=acc[i][2]=acc[i][3]=0.f;}

    float4 va[4], vb[4];
    load4(Asrc, Hn, tid, va);
    {   const float* wp = wd + (tid&1)*16;
#pragma unroll
        for (int j=0;j<4;j++){ float4 w=*(const float4*)(wp+j*4); va[j].x*=w.x; va[j].y*=w.y; va[j].z*=w.z; va[j].w*=w.w; } }
    load4(Bsrc, Hn, tid, vb);

    for (int kt=0; kt<32; ++kt){
        __syncthreads();
        store_split(va, sm, TAH, TAL, tid);
        store_split(vb, sm, TBH, TBL, tid);
        if (kt < 31){
            load4(Asrc + (kt+1)*32, Hn, tid, va);
            const float* wp = wd + (kt+1)*32 + (tid&1)*16;
#pragma unroll
            for (int j=0;j<4;j++){ float4 w=*(const float4*)(wp+j*4); va[j].x*=w.x; va[j].y*=w.y; va[j].z*=w.z; va[j].w*=w.w; }
            load4(Bsrc + (kt+1)*32, Hn, tid, vb);
        }
        __syncthreads();
        mma_chunk(sb+TAH, sb+TAL, sb+TBH, sb+TBL, acc, lane, wm, wn);
    }

    const float bias = wcb[0];
    const int qrow = lane>>2, qc = (lane&3)*2;
#pragma unroll
    for (int mi=0;mi<2;mi++){
        const int m = m0 + wm + mi*16 + qrow;
        const float sd0 = g_sd[b*Dn + m] + bias;
        const float sd1 = g_sd[b*Dn + m + 8] + bias;
#pragma unroll
        for (int ni=0;ni<8;ni++){
            const int n = wn + ni*8 + qc;
            const float2 sq = *(const float2*)(g_sq + b*Qn + n);
            float* o0 = g_S + ((size_t)b*Dn + m)*Qn + n;
            const float* c = acc[mi*8+ni];
            *(float2*)o0          = make_float2(c[0]+sd0+sq.x, c[1]+sd0+sq.y);
            *(float2*)(o0 + 8*Qn) = make_float2(c[2]+sd1+sq.x, c[3]+sd1+sq.y);
        }
    }
}

// ---------------- K2: row softmax over q -> g_P ----------------
__global__ void k2_rowsoftmax(const int* __restrict__ qmask, const int* __restrict__ dmask)
{
    const int row  = (blockIdx.x * blockDim.x + threadIdx.x) >> 5;
    const int lane = threadIdx.x & 31;
    if (row >= Bn*Dn) return;
    const int b = row >> 10;
    const float4 s = *(const float4*)(g_S + (size_t)row*Qn + lane*4);
    const int dm = dmask[row];
    const int4 qm = *(const int4*)(qmask + b*Qn + lane*4);
    const bool m0v = (dm > 0) && (qm.x > 0);
    const bool m1v = (dm > 0) && (qm.y > 0);
    const bool m2v = (dm > 0) && (qm.z > 0);
    const bool m3v = (dm > 0) && (qm.w > 0);
    const float l0 = m0v ? s.x : NEGINF;
    const float l1 = m1v ? s.y : NEGINF;
    const float l2 = m2v ? s.z : NEGINF;
    const float l3 = m3v ? s.w : NEGINF;
    float mx = fmaxf(fmaxf(l0, l1), fmaxf(l2, l3));
#pragma unroll
    for (int o = 16; o; o >>= 1) mx = fmaxf(mx, __shfl_xor_sync(0xffffffffu, mx, o));
    const float e0 = __expf(l0 - mx), e1 = __expf(l1 - mx);
    const float e2 = __expf(l2 - mx), e3 = __expf(l3 - mx);
    float sme = e0 + e1 + e2 + e3;
#pragma unroll
    for (int o = 16; o; o >>= 1) sme += __shfl_xor_sync(0xffffffffu, sme, o);
    const float inv = 1.f / sme;
    *(float4*)(g_P + (size_t)row*Qn + lane*4) =
        make_float4(m0v ? e0*inv : 0.f, m1v ? e1*inv : 0.f, m2v ? e2*inv : 0.f, m3v ? e3*inv : 0.f);
}

// ---------------- K3: column softmax over d -> g_P2t (transposed out) ----------------
__global__ void __launch_bounds__(1024)
k3_colsoftmax(const int* __restrict__ qmask, const int* __restrict__ dmask)
{
    const int b  = blockIdx.y;
    const int tx = threadIdx.x, ty = threadIdx.y;
    const int q0 = blockIdx.x*32;
    const int q  = q0 + tx;
    __shared__ float red[32][33];
    __shared__ float trn[32][33];
    const int qm = qmask[b*Qn + q];
    float v[32];
    float mx = -3.0e38f;
#pragma unroll
    for (int j = 0; j < 32; ++j) {
        const int d = ty + j*32;
        const float s = g_S[((size_t)b*Dn + d)*Qn + q];
        const float l = (qm > 0 && dmask[b*Dn + d] > 0) ? s : NEGINF;
        v[j] = l; mx = fmaxf(mx, l);
    }
    red[ty][tx] = mx; __syncthreads();
#pragma unroll
    for (int off = 16; off; off >>= 1) {
        if (ty < off) red[ty][tx] = fmaxf(red[ty][tx], red[ty+off][tx]);
        __syncthreads();
    }
    mx = red[0][tx];
    __syncthreads();
    float se = 0.f;
#pragma unroll
    for (int j = 0; j < 32; ++j) { v[j] = __expf(v[j] - mx); se += v[j]; }
    red[ty][tx] = se; __syncthreads();
#pragma unroll
    for (int off = 16; off; off >>= 1) {
        if (ty < off) red[ty][tx] += red[ty+off][tx];
        __syncthreads();
    }
    const float inv = 1.f / red[0][tx];
    __syncthreads();
    for (int j = 0; j < 32; ++j) {
        const int d = ty + j*32;
        const float ind = (qm > 0 && dmask[b*Dn + d] > 0) ? 1.f : 0.f;
        trn[ty][tx] = v[j]*inv*ind;      // (d = j*32+ty, q = q0+tx)
        __syncthreads();
        g_P2t[((size_t)b*Qn + q0 + ty)*Dn + j*32 + tx] = trn[tx][ty];
        __syncthreads();
    }
}

// ---------------- K4: T^T[h][q] = sum_d Ud^T[h][d] * P2t[q][d] ----------------
// grid (8,16), 256 thr, dsmem 57856. A transposed (staged), B direct.
__global__ void __launch_bounds__(256)
k4_T(const float* __restrict__ Ud)
{
    extern __shared__ __align__(16) char sm[];
    float* stg = (float*)(sm + STG_OFF);
    const int tid = threadIdx.x, lane = tid&31, wid = tid>>5;
    const int b = blockIdx.y, h0 = blockIdx.x*128;
    const int wm = (wid&3)*32, wn = (wid>>2)*64;
    const uint32_t sb = smem_u32(sm);

    const float* Atsrc = Ud + (size_t)b*Dn*Hn + h0;    // rows d, cols h
    const float* Bsrc  = g_P2t + (size_t)b*Qn*Dn;      // [q][d]

    float acc[16][4];
#pragma unroll
    for (int i=0;i<16;i++){acc[i][0]=acc[i][1]=acc[i][2]=acc[i][3]=0.f;}

    float4 va[4], vb[4];
    load_stage(Atsrc, Hn, tid, va);
    load4(Bsrc, Dn, tid, vb);

    for (int kt=0; kt<32; ++kt){
        __syncthreads();
        store_stage(va, stg, tid);
        store_split(vb, sm, TBH, TBL, tid);
        if (kt < 31){
            load_stage(Atsrc + (size_t)(kt+1)*32*Hn, Hn, tid, va);
            load4(Bsrc + (kt+1)*32, Dn, tid, vb);
        }
        __syncthreads();
        trans_convert(stg, sm, TAH, TAL, tid);
        __syncthreads();
        mma_chunk(sb+TAH, sb+TAL, sb+TBH, sb+TBL, acc, lane, wm, wn);
    }

    const int qrow = lane>>2, qc = (lane&3)*2;
#pragma unroll
    for (int mi=0;mi<2;mi++){
        const int m = h0 + wm + mi*16 + qrow;
#pragma unroll
        for (int ni=0;ni<8;ni++){
            const int n = wn + ni*8 + qc;
            float* o0 = g_Tt + ((size_t)b*Hn + m)*Qn + n;
            const float* c = acc[mi*8+ni];
            *(float2*)o0          = make_float2(c[0], c[1]);
            *(float2*)(o0 + 8*Qn) = make_float2(c[2], c[3]);
        }
    }
}

// ---------------- K5a: A_d2q = P @ Uq ; write segments 0,1,2 ----------------
// grid (8, 8, 16), 256 thr, dsmem 57856. A direct (g_P), B transposed (Uq, staged).
__global__ void __launch_bounds__(256)
k5a_out(const float* __restrict__ Ud, const float* __restrict__ Uq,
        float* __restrict__ out)
{
    extern __shared__ __align__(16) char sm[];
    float* stg = (float*)(sm + STG_OFF);
    const int tid = threadIdx.x, lane = tid&31, wid = tid>>5;
    const int b = blockIdx.z, m0 = blockIdx.y*128, h0 = blockIdx.x*128;
    const int wm = (wid&3)*32, wn = (wid>>2)*64;
    const uint32_t sb = smem_u32(sm);

    const float* Asrc  = g_P + ((size_t)b*Dn + m0)*Qn;   // [d][q]
    const float* Btsrc = Uq + (size_t)b*Qn*Hn + h0;      // rows q, cols h

    float acc[16][4];
#pragma unroll
    for (int i=0;i<16;i++){acc[i][0]=acc[i][1]=acc[i][2]=acc[i][3]=0.f;}

    float4 va[4], vb[4];
    load4(Asrc, Qn, tid, va);
    load_stage(Btsrc, Hn, tid, vb);

    for (int kt=0; kt<4; ++kt){
        __syncthreads();
        store_split(va, sm, TAH, TAL, tid);
        store_stage(vb, stg, tid);
        if (kt < 3){
            load4(Asrc + (kt+1)*32, Qn, tid, va);
            load_stage(Btsrc + (size_t)(kt+1)*32*Hn, Hn, tid, vb);
        }
        __syncthreads();
        trans_convert(stg, sm, TBH, TBL, tid);
        __syncthreads();
        mma_chunk(sb+TAH, sb+TAL, sb+TBH, sb+TBL, acc, lane, wm, wn);
    }

    const int qrow = lane>>2, qc = (lane&3)*2;
#pragma unroll
    for (int mi=0;mi<2;mi++){
        const int m = m0 + wm + mi*16 + qrow;
#pragma unroll
        for (int ni=0;ni<8;ni++){
            const int h = h0 + wn + ni*8 + qc;
            const float* c = acc[mi*8+ni];
            const float2 u0 = *(const float2*)(Ud + ((size_t)b*Dn + m)*Hn + h);
            const float2 u1 = *(const float2*)(Ud + ((size_t)b*Dn + m + 8)*Hn + h);
            float* o0 = out + ((size_t)b*Dn + m)*(4*Hn) + h;
            float* o1 = o0 + (size_t)8*(4*Hn);
            *(float2*)(o0)        = u0;
            *(float2*)(o0 + Hn)   = make_float2(c[0], c[1]);
            *(float2*)(o0 + 2*Hn) = make_float2(u0.x*c[0], u0.y*c[1]);
            *(float2*)(o1)        = u1;
            *(float2*)(o1 + Hn)   = make_float2(c[2], c[3]);
            *(float2*)(o1 + 2*Hn) = make_float2(u1.x*c[2], u1.y*c[3]);
        }
    }
}

// ---------------- K5b: A_q2d = P @ T ; write segment 3 ----------------
// grid (8, 8, 16), 256 thr, dsmem 40960. A direct (g_P), B direct (g_Tt K-major).
__global__ void __launch_bounds__(256)
k5b_out(const float* __restrict__ Ud, float* __restrict__ out)
{
    extern __shared__ __align__(16) char sm[];
    const int tid = threadIdx.x, lane = tid&31, wid = tid>>5;
    const int b = blockIdx.z, m0 = blockIdx.y*128, h0 = blockIdx.x*128;
    const int wm = (wid&3)*32, wn = (wid>>2)*64;
    const uint32_t sb = smem_u32(sm);

    const float* Asrc = g_P + ((size_t)b*Dn + m0)*Qn;    // [d][q]
    const float* Bsrc = g_Tt + ((size_t)b*Hn + h0)*Qn;   // [h][q]

    float acc[16][4];
#pragma unroll
    for (int i=0;i<16;i++){acc[i][0]=acc[i][1]=acc[i][2]=acc[i][3]=0.f;}

    float4 va[4], vb[4];
    load4(Asrc, Qn, tid, va);
    load4(Bsrc, Qn, tid, vb);

    for (int kt=0; kt<4; ++kt){
        __syncthreads();
        store_split(va, sm, TAH, TAL, tid);
        store_split(vb, sm, TBH, TBL, tid);
        if (kt < 3){
            load4(Asrc + (kt+1)*32, Qn, tid, va);
            load4(Bsrc + (kt+1)*32, Qn, tid, vb);
        }
        __syncthreads();
        mma_chunk(sb+TAH, sb+TAL, sb+TBH, sb+TBL, acc, lane, wm, wn);
    }

    const int qrow = lane>>2, qc = (lane&3)*2;
#pragma unroll
    for (int mi=0;mi<2;mi++){
        const int m = m0 + wm + mi*16 + qrow;
#pragma unroll
        for (int ni=0;ni<8;ni++){
            const int h = h0 + wn + ni*8 + qc;
            const float* c = acc[mi*8+ni];
            const float2 u0 = *(const float2*)(Ud + ((size_t)b*Dn + m)*Hn + h);
            const float2 u1 = *(const float2*)(Ud + ((size_t)b*Dn + m + 8)*Hn + h);
            float* o0 = out + ((size_t)b*Dn + m)*(4*Hn) + 3*Hn + h;
            float* o1 = o0 + (size_t)8*(4*Hn);
            *(float2*)o0 = make_float2(u0.x*c[0], u0.y*c[1]);
            *(float2*)o1 = make_float2(u1.x*c[2], u1.y*c[3]);
        }
    }
}

// ---------------- launch ----------------
#define SMEM_DIRECT 40960
#define SMEM_STAGED (40960 + 16896)

extern "C" void kernel_launch(void* const* d_in, const int* in_sizes, int n_in,
                              void* d_out, int out_size)
{
    const float* Ud    = (const float*)d_in[0];
    const float* Uq    = (const float*)d_in[1];
    const float* wc    = (const float*)d_in[2];
    const float* wcb   = (const float*)d_in[3];
    const int*   qmask = (const int*)d_in[4];
    const int*   dmask = (const int*)d_in[5];
    float* out = (float*)d_out;
    (void)in_sizes; (void)n_in; (void)out_size;

    static bool attr_done = false;
    if (!attr_done) {
        cudaFuncSetAttribute(k4_T,   cudaFuncAttributeMaxDynamicSharedMemorySize, SMEM_STAGED);
        cudaFuncSetAttribute(k5a_out, cudaFuncAttributeMaxDynamicSharedMemorySize, SMEM_STAGED);
        attr_done = true;
    }

    const int nrows = Bn*Dn + Bn*Qn;
    k0_rowdots   <<<(nrows + 7)/8, 256>>>(Ud, Uq, wc);
    k1_score     <<<dim3(Dn/128, Bn), 256, SMEM_DIRECT>>>(Ud, Uq, wc, wcb);
    k2_rowsoftmax<<<(Bn*Dn)/8, 256>>>(qmask, dmask);
    k3_colsoftmax<<<dim3(Qn/32, Bn), dim3(32, 32)>>>(qmask, dmask);
    k4_T         <<<dim3(Hn/128, Bn), 256, SMEM_STAGED>>>(Ud);
    k5a_out      <<<dim3(Hn/128, Dn/128, Bn), 256, SMEM_STAGED>>>(Ud, Uq, out);
    k5b_out      <<<dim3(Hn/128, Dn/128, Bn), 256, SMEM_DIRECT>>>(Ud, out);
}